// round 15
// baseline (speedup 1.0000x reference)
#include <cuda_runtime.h>
#include <cuda_bf16.h>
#include <stdint.h>

#define N_NODES 100000
#define N_EDGES 1200000
#define D 64

// Persistent scratch: agg = scatter_sum(relu(x[src] + e)); zeroed by memset.
__device__ __align__(16) float g_agg[(size_t)N_NODES * D];

// ---------------------------------------------------------------------------
// Kernel 1: per-edge message + scatter reduce (L2-transit bound, unchanged).
// ---------------------------------------------------------------------------
__global__ void edge_kernel(const float* __restrict__ x,
                            const int* __restrict__ ei,
                            const float* __restrict__ ea) {
    int t = blockIdx.x * blockDim.x + threadIdx.x;
    const int total = N_EDGES * 16;
    if (t >= total) return;
    int e = t >> 4;
    int c = t & 15;

    int src = __ldg(ei + e);
    int dst = __ldg(ei + N_EDGES + e);

    float4 xv = __ldg(reinterpret_cast<const float4*>(x) + (size_t)src * (D / 4) + c);
    float4 ev = __ldcs(reinterpret_cast<const float4*>(ea) + (size_t)e * (D / 4) + c);

    float4 m;
    m.x = fmaxf(xv.x + ev.x, 0.0f);
    m.y = fmaxf(xv.y + ev.y, 0.0f);
    m.z = fmaxf(xv.z + ev.z, 0.0f);
    m.w = fmaxf(xv.w + ev.w, 0.0f);

    float* p = g_agg + (size_t)dst * D + c * 4;
    asm volatile("red.global.add.v4.f32 [%0], {%1, %2, %3, %4};"
                 :: "l"(p), "f"(m.x), "f"(m.y), "f"(m.z), "f"(m.w)
                 : "memory");
}

// ---------------------------------------------------------------------------
// Kernel 2: bf16 split-precision mma.sync MLP.
//   out = relu((x+agg) @ W1 + b1) @ W2 + b2
//
// mma.sync.aligned.m16n8k16.row.col.f32.bf16.bf16.f32 (baseline PTX, HMMA).
// 2-term bf16 split: D = Ahi*Bhi + Ahi*Blo + Alo*Bhi, fp32 accumulate.
// Block = 128 thr / 4 warps, tile = 64 nodes. Warp w: rows w*16..+15,
// all 8 N-tiles, K in 4 chunks of 16. A row-major [n][k], B col-major
// [j][k], both stride 72 bf16 (36 words): fragment loads (lane pattern
// g=lane>>2, t=lane&3 -> word g*36 + t + kc/2) hit 32 distinct banks.
// ---------------------------------------------------------------------------
#define AS 72                       // bf16 elems per row (144 B, 36 words)
#define SM_AHI 0
#define SM_ALO (64 * AS)            // bf16 element offsets
#define SM_BHI (2 * 64 * AS)
#define SM_BLO (3 * 64 * AS)
#define SMEM_MLP_BYTES (4 * 64 * AS * 2)   // 36864 B

__device__ __forceinline__ void mma_bf16(float d[4],
                                         uint32_t a0, uint32_t a1,
                                         uint32_t a2, uint32_t a3,
                                         uint32_t b0, uint32_t b1) {
    asm volatile(
        "mma.sync.aligned.m16n8k16.row.col.f32.bf16.bf16.f32 "
        "{%0,%1,%2,%3}, {%4,%5,%6,%7}, {%8,%9}, {%0,%1,%2,%3};"
        : "+f"(d[0]), "+f"(d[1]), "+f"(d[2]), "+f"(d[3])
        : "r"(a0), "r"(a1), "r"(a2), "r"(a3), "r"(b0), "r"(b1));
}

__device__ __forceinline__ uint32_t pack_bf16x2(float lo, float hi) {
    __nv_bfloat162 p;
    p.x = __float2bfloat16(lo);
    p.y = __float2bfloat16(hi);
    return *reinterpret_cast<uint32_t*>(&p);
}

// Stage B[j][k] = W[k][j] as bf16 hi/lo.
__device__ __forceinline__ void stage_B(const float* __restrict__ W,
                                        __nv_bfloat16* Bhi, __nv_bfloat16* Blo) {
    for (int i = threadIdx.x; i < 64 * 16; i += 128) {
        int k = i >> 4, c = i & 15;
        float4 w = __ldg(reinterpret_cast<const float4*>(W) + i);
        float wv[4] = {w.x, w.y, w.z, w.w};
        #pragma unroll
        for (int q = 0; q < 4; ++q) {
            int j = c * 4 + q;
            __nv_bfloat16 hi = __float2bfloat16(wv[q]);
            __nv_bfloat16 lo = __float2bfloat16(wv[q] - __bfloat162float(hi));
            Bhi[j * AS + k] = hi;
            Blo[j * AS + k] = lo;
        }
    }
}

__global__ void __launch_bounds__(128)
mlp_mma_kernel(const float* __restrict__ x,
               const float* __restrict__ W1, const float* __restrict__ b1,
               const float* __restrict__ W2, const float* __restrict__ b2,
               float* __restrict__ out) {
    extern __shared__ __align__(16) __nv_bfloat16 sm[];
    __nv_bfloat16* Ahi = sm + SM_AHI;
    __nv_bfloat16* Alo = sm + SM_ALO;
    __nv_bfloat16* Bhi = sm + SM_BHI;
    __nv_bfloat16* Blo = sm + SM_BLO;

    const int tid = threadIdx.x;
    const int node0 = blockIdx.x * 64;

    // Stage A = h = x + agg (EPS=0) as bf16 hi/lo, row-major [n][k].
    {
        const float4* ag = reinterpret_cast<const float4*>(g_agg);
        const float4* xg = reinterpret_cast<const float4*>(x);
        #pragma unroll
        for (int i = tid; i < 64 * 16; i += 128) {
            int n = i >> 4, c = i & 15;
            int node = node0 + n;
            if (node >= N_NODES) node = N_NODES - 1;
            size_t gi = (size_t)node * 16 + c;
            float4 a = ag[gi];
            float4 v = __ldg(xg + gi);
            float hv[4] = {a.x + v.x, a.y + v.y, a.z + v.z, a.w + v.w};
            float hi[4], lo[4];
            #pragma unroll
            for (int q = 0; q < 4; ++q) {
                hi[q] = __bfloat162float(__float2bfloat16(hv[q]));
                lo[q] = hv[q] - hi[q];
            }
            uint2 phi = make_uint2(pack_bf16x2(hi[0], hi[1]), pack_bf16x2(hi[2], hi[3]));
            uint2 plo = make_uint2(pack_bf16x2(lo[0], lo[1]), pack_bf16x2(lo[2], lo[3]));
            *reinterpret_cast<uint2*>(Ahi + n * AS + c * 4) = phi;
            *reinterpret_cast<uint2*>(Alo + n * AS + c * 4) = plo;
        }
    }
    stage_B(W1, Bhi, Blo);
    __syncthreads();

    const int lane = tid & 31;
    const int g = lane >> 2;         // 0..7
    const int t = lane & 3;          // 0..3
    const int m0 = (tid >> 5) * 16;  // warp's M-tile base row

    float acc[8][4];
    #pragma unroll
    for (int nt = 0; nt < 8; ++nt)
        #pragma unroll
        for (int r = 0; r < 4; ++r) acc[nt][r] = 0.0f;

    // ---- Layer 1 ----
    #pragma unroll
    for (int kc = 0; kc < 64; kc += 16) {
        const int ra = (m0 + g) * AS + kc + 2 * t;
        const int rb = (m0 + g + 8) * AS + kc + 2 * t;
        uint32_t ah0 = *reinterpret_cast<const uint32_t*>(Ahi + ra);
        uint32_t ah1 = *reinterpret_cast<const uint32_t*>(Ahi + rb);
        uint32_t ah2 = *reinterpret_cast<const uint32_t*>(Ahi + ra + 8);
        uint32_t ah3 = *reinterpret_cast<const uint32_t*>(Ahi + rb + 8);
        uint32_t al0 = *reinterpret_cast<const uint32_t*>(Alo + ra);
        uint32_t al1 = *reinterpret_cast<const uint32_t*>(Alo + rb);
        uint32_t al2 = *reinterpret_cast<const uint32_t*>(Alo + ra + 8);
        uint32_t al3 = *reinterpret_cast<const uint32_t*>(Alo + rb + 8);
        #pragma unroll
        for (int nt = 0; nt < 8; ++nt) {
            const int cb = (nt * 8 + g) * AS + kc + 2 * t;
            uint32_t bh0 = *reinterpret_cast<const uint32_t*>(Bhi + cb);
            uint32_t bh1 = *reinterpret_cast<const uint32_t*>(Bhi + cb + 8);
            uint32_t bl0 = *reinterpret_cast<const uint32_t*>(Blo + cb);
            uint32_t bl1 = *reinterpret_cast<const uint32_t*>(Blo + cb + 8);
            mma_bf16(acc[nt], ah0, ah1, ah2, ah3, bh0, bh1);
            mma_bf16(acc[nt], ah0, ah1, ah2, ah3, bl0, bl1);
            mma_bf16(acc[nt], al0, al1, al2, al3, bh0, bh1);
        }
    }
    __syncthreads();   // all reads of A (h) and B (W1) complete

    // Epilogue 1: t = relu(acc + b1) -> back into Ahi/Alo (rows m0+g, m0+g+8).
    #pragma unroll
    for (int nt = 0; nt < 8; ++nt) {
        int col = nt * 8 + 2 * t;
        float2 bb = __ldg(reinterpret_cast<const float2*>(b1 + col));
        float v0 = fmaxf(acc[nt][0] + bb.x, 0.0f);
        float v1 = fmaxf(acc[nt][1] + bb.y, 0.0f);
        float v2 = fmaxf(acc[nt][2] + bb.x, 0.0f);
        float v3 = fmaxf(acc[nt][3] + bb.y, 0.0f);
        float h0 = __bfloat162float(__float2bfloat16(v0));
        float h1 = __bfloat162float(__float2bfloat16(v1));
        float h2 = __bfloat162float(__float2bfloat16(v2));
        float h3 = __bfloat162float(__float2bfloat16(v3));
        *reinterpret_cast<uint32_t*>(Ahi + (m0 + g) * AS + col)     = pack_bf16x2(h0, h1);
        *reinterpret_cast<uint32_t*>(Ahi + (m0 + g + 8) * AS + col) = pack_bf16x2(h2, h3);
        *reinterpret_cast<uint32_t*>(Alo + (m0 + g) * AS + col)     = pack_bf16x2(v0 - h0, v1 - h1);
        *reinterpret_cast<uint32_t*>(Alo + (m0 + g + 8) * AS + col) = pack_bf16x2(v2 - h2, v3 - h3);
        acc[nt][0] = 0.0f; acc[nt][1] = 0.0f; acc[nt][2] = 0.0f; acc[nt][3] = 0.0f;
    }
    stage_B(W2, Bhi, Blo);
    __syncthreads();

    // ---- Layer 2 ----
    #pragma unroll
    for (int kc = 0; kc < 64; kc += 16) {
        const int ra = (m0 + g) * AS + kc + 2 * t;
        const int rb = (m0 + g + 8) * AS + kc + 2 * t;
        uint32_t ah0 = *reinterpret_cast<const uint32_t*>(Ahi + ra);
        uint32_t ah1 = *reinterpret_cast<const uint32_t*>(Ahi + rb);
        uint32_t ah2 = *reinterpret_cast<const uint32_t*>(Ahi + ra + 8);
        uint32_t ah3 = *reinterpret_cast<const uint32_t*>(Ahi + rb + 8);
        uint32_t al0 = *reinterpret_cast<const uint32_t*>(Alo + ra);
        uint32_t al1 = *reinterpret_cast<const uint32_t*>(Alo + rb);
        uint32_t al2 = *reinterpret_cast<const uint32_t*>(Alo + ra + 8);
        uint32_t al3 = *reinterpret_cast<const uint32_t*>(Alo + rb + 8);
        #pragma unroll
        for (int nt = 0; nt < 8; ++nt) {
            const int cb = (nt * 8 + g) * AS + kc + 2 * t;
            uint32_t bh0 = *reinterpret_cast<const uint32_t*>(Bhi + cb);
            uint32_t bh1 = *reinterpret_cast<const uint32_t*>(Bhi + cb + 8);
            uint32_t bl0 = *reinterpret_cast<const uint32_t*>(Blo + cb);
            uint32_t bl1 = *reinterpret_cast<const uint32_t*>(Blo + cb + 8);
            mma_bf16(acc[nt], ah0, ah1, ah2, ah3, bh0, bh1);
            mma_bf16(acc[nt], ah0, ah1, ah2, ah3, bl0, bl1);
            mma_bf16(acc[nt], al0, al1, al2, al3, bh0, bh1);
        }
    }

    // Final epilogue: out = acc + b2 (guarded float2 stores).
    int nodeA = node0 + m0 + g;
    int nodeB = nodeA + 8;
    #pragma unroll
    for (int nt = 0; nt < 8; ++nt) {
        int col = nt * 8 + 2 * t;
        float2 bb = __ldg(reinterpret_cast<const float2*>(b2 + col));
        if (nodeA < N_NODES) {
            float2 v = make_float2(acc[nt][0] + bb.x, acc[nt][1] + bb.y);
            *reinterpret_cast<float2*>(out + (size_t)nodeA * D + col) = v;
        }
        if (nodeB < N_NODES) {
            float2 v = make_float2(acc[nt][2] + bb.x, acc[nt][3] + bb.y);
            *reinterpret_cast<float2*>(out + (size_t)nodeB * D + col) = v;
        }
    }
}

// ---------------------------------------------------------------------------
// Launch.
// ---------------------------------------------------------------------------
extern "C" void kernel_launch(void* const* d_in, const int* in_sizes, int n_in,
                              void* d_out, int out_size) {
    const float* x   = (const float*)d_in[0];
    const int*   ei  = (const int*)d_in[1];
    const float* ea  = (const float*)d_in[2];
    const float* W1  = (const float*)d_in[3];
    const float* b1  = (const float*)d_in[4];
    const float* W2  = (const float*)d_in[5];
    const float* b2  = (const float*)d_in[6];
    float*       out = (float*)d_out;

    // agg <- 0 (graph-capturable)
    void* aggp = nullptr;
    cudaGetSymbolAddress(&aggp, g_agg);
    cudaMemsetAsync(aggp, 0, sizeof(float) * (size_t)N_NODES * D);

    {   // scatter-sum messages
        int total = N_EDGES * 16;
        edge_kernel<<<(total + 255) / 256, 256>>>(x, ei, ea);
    }
    {   // tensor-core (mma.sync) MLP: 1563 tiles of 64 nodes
        int grid = (N_NODES + 63) / 64;
        mlp_mma_kernel<<<grid, 128, SMEM_MLP_BYTES>>>(x, W1, b1, W2, b2, out);
    }
}